// round 16
// baseline (speedup 1.0000x reference)
#include <cuda_runtime.h>

#define NB 8192      // batch
#define NK 32        // clusters
#define ND 128       // latent dim
#define NORD 8       // AR order
#define NT 24        // output length
#define NE 16        // exogenous dim
#define NIN 96       // input length
#define TB 8         // batch rows per block (1 warp per b)
#define THREADS 256  // 8 warps; warp w owns batch row w; lane = cluster k
#define ROWF 132     // padded float row stride (132 mod 32 = 4: conflict-free f4 rows)

// Scratch (no cudaMalloc). Flags are 0-init at module load and only ever go
// 0 -> 1; all flag states give correct results (set = slower path). Data
// tables are rewritten by prep on every call (deterministic).
__device__ __align__(16) float g_nmuF[NK * ND];  // -mu, [k][d]
__device__ __align__(16) float g_dg0F[ND];       // diag^2 of k=0, per d
__device__ __align__(16) float g_dgKD[NK * ND];  // diag^2, [k][d] (per-k path)
__device__ int g_general;    // any off-diagonal nonzero -> full quadratic form
__device__ int g_nonuni;     // diag^2 differs across k  -> per-k path
__device__ int g_notscalar;  // diag^2 differs across d  -> per-d path

// grid = 32 blocks per k (1024 blocks), 128 threads; 1 float4 scan per thread.
// Blocks 0..31 additionally pack the -mu table (k = blockIdx.x).
__global__ void prep_kernel(const float* __restrict__ sinv,
                            const float* __restrict__ mu) {
    const int k = blockIdx.x >> 5;
    const int q = blockIdx.x & 31;
    const int t = threadIdx.x;
    const float s00 = sinv[0];
    const float dg00 = s00 * s00;
    const float* S = sinv + k * ND * ND;
    int bad = 0;
    {
        int rl = t >> 5, c = t & 31;        // row-local (0..3), float4 column
        int row = q * 4 + rl;
        float4 v = *reinterpret_cast<const float4*>(S + row * ND + c * 4);
        int base = c * 4;
        if (base + 0 != row && v.x != 0.0f) bad = 1;
        if (base + 1 != row && v.y != 0.0f) bad = 1;
        if (base + 2 != row && v.z != 0.0f) bad = 1;
        if (base + 3 != row && v.w != 0.0f) bad = 1;
        if (row >= base && row < base + 4) {
            float dv = (row == base) ? v.x : (row == base + 1) ? v.y
                     : (row == base + 2) ? v.z : v.w;
            float dg = dv * dv;
            g_dgKD[k * ND + row] = dg;
            if (dg != dg00) g_notscalar = 1;             // benign race 0->1
            float d0 = sinv[row * ND + row];             // k=0 same-row diag
            if (dg != d0 * d0) g_nonuni = 1;             // benign race 0->1
        }
    }
    if (bad) g_general = 1;                              // benign race 0->1

    // pack tables (first 32 blocks: one k each)
    if (blockIdx.x < NK) {
        int pk = blockIdx.x;
        g_nmuF[pk * ND + t] = -mu[pk * ND + t];
        if (pk == 0) {
            float dv = sinv[t * ND + t];   // k = 0 diagonal
            g_dg0F[t] = dv * dv;
        }
    }
}

__global__ __launch_bounds__(THREADS, 7)
void fused_kernel(const float* __restrict__ y,
                  const float* __restrict__ z,
                  const float* __restrict__ u,
                  const float* __restrict__ mu,
                  const float* __restrict__ sinv,
                  const float* __restrict__ A,
                  const float* __restrict__ Bx,
                  const float* __restrict__ bias,
                  float* __restrict__ out)
{
    __shared__ __align__(16) float nm_s[NK][ROWF];   // -mu rows, 16.9KB
    __shared__ __align__(16) float z_s[TB][ROWF];    // raw z rows, 4.2KB
    __shared__ __align__(16) float u_s[TB][NE];
    __shared__ __align__(16) float A_s[NK][NORD + 1];   // stride 9 (coprime 32)
    __shared__ __align__(16) float Bx_s[NK][NE + 1];    // stride 17 (coprime 32)
    __shared__ __align__(16) float bias_s[NK];
    __shared__ __align__(16) float yh_s[TB][NORD];
    __shared__ __align__(16) float rinv_s[TB];          // 1/sum(w) per b
    __shared__ __align__(16) float part2[TB][4][28];    // AR partials (4 per b)

    const int t  = threadIdx.x;
    const int b0 = blockIdx.x * TB;
    const int gen   = g_general;
    const int nonu  = g_nonuni;
    const int notsc = g_notscalar;

    // ---- zero this block's x_recon slice (overlaps with staging) ----
    if (t < TB * NIN / 4) {   // 192 float4
        float4 z4 = make_float4(0.f, 0.f, 0.f, 0.f);
        reinterpret_cast<float4*>(out + NB * NT + b0 * NIN)[t] = z4;
    }

    // ---- cooperative staging ----
    {   // z: 256 float4 = 1 per thread
        float4 v = reinterpret_cast<const float4*>(z + b0 * ND)[t];
        int row = t >> 5, c = t & 31;
        *reinterpret_cast<float4*>(&z_s[row][c * 4]) = v;
    }
    {   // nm table: 16KB = 1024 float4, 4 per thread
        const float4* src = reinterpret_cast<const float4*>(g_nmuF);
        #pragma unroll
        for (int j = 0; j < NK * ND / 4 / THREADS; j++) {   // 4 iters
            int i4 = j * THREADS + t;
            float4 v = src[i4];
            int k_ = i4 >> 5, c = i4 & 31;
            *reinterpret_cast<float4*>(&nm_s[k_][c * 4]) = v;
        }
    }
    if (t < TB * NE) u_s[t >> 4][t & 15] = u[(b0 + (t >> 4)) * NE + (t & 15)];
    A_s[t >> 3][t & 7] = A[t];                     // 256 entries, 1 per thread
    #pragma unroll
    for (int j = 0; j < 2; j++) {                  // Bx: 512 entries
        int i = j * THREADS + t;
        Bx_s[i >> 4][i & 15] = Bx[i];
    }
    if (t < NK) bias_s[t] = bias[t];
    if (t < TB * NORD)
        yh_s[t >> 3][t & 7] = y[(b0 + (t >> 3)) * NIN + (NIN - NORD) + (t & 7)];
    __syncthreads();

    const int bl = t >> 5;    // local batch row = warp id (0..7)
    const int k  = t & 31;    // cluster owned by this lane

    // ---- squared Mahalanobis distance, frozen op sequence per cluster:
    //      g = z + (-mu); gg = g*g; acc = fmaf(dg, gg, acc), d ascending.
    //      (Bit-identical to the packed fp32x2 lanes of prior rounds.) ----
    float d2v;
    const float* zr = &z_s[bl][0];   // warp-wide broadcast reads
    const float* nr = &nm_s[k][0];   // per-lane row, conflict-free f4
    if (gen == 0) {
        float acc = 0.0f;
        if (nonu == 0) {
            if (notsc == 0) {
                const float dg = g_dg0F[0];   // scalar diag^2 everywhere
                #pragma unroll 8
                for (int d = 0; d < ND; d += 4) {
                    float4 zq = *reinterpret_cast<const float4*>(&zr[d]);
                    float4 nm = *reinterpret_cast<const float4*>(&nr[d]);
                    float g0 = zq.x + nm.x; acc = fmaf(dg, g0 * g0, acc);
                    float g1 = zq.y + nm.y; acc = fmaf(dg, g1 * g1, acc);
                    float g2 = zq.z + nm.z; acc = fmaf(dg, g2 * g2, acc);
                    float g3 = zq.w + nm.w; acc = fmaf(dg, g3 * g3, acc);
                }
            } else {
                // per-d diag^2 (uniform across k), float4 from gmem/L1
                #pragma unroll 4
                for (int d = 0; d < ND; d += 4) {
                    float4 zq = *reinterpret_cast<const float4*>(&zr[d]);
                    float4 nm = *reinterpret_cast<const float4*>(&nr[d]);
                    float4 dq = *reinterpret_cast<const float4*>(&g_dg0F[d]);
                    float g0 = zq.x + nm.x; acc = fmaf(dq.x, g0 * g0, acc);
                    float g1 = zq.y + nm.y; acc = fmaf(dq.y, g1 * g1, acc);
                    float g2 = zq.z + nm.z; acc = fmaf(dq.z, g2 * g2, acc);
                    float g3 = zq.w + nm.w; acc = fmaf(dq.w, g3 * g3, acc);
                }
            }
        } else {
            // per-k diag^2, lane-private rows from gmem (L1-resident 16KB)
            #pragma unroll 4
            for (int d = 0; d < ND; d += 4) {
                float4 zq = *reinterpret_cast<const float4*>(&zr[d]);
                float4 nm = *reinterpret_cast<const float4*>(&nr[d]);
                float4 dq = *reinterpret_cast<const float4*>(&g_dgKD[k * ND + d]);
                float g0 = zq.x + nm.x; acc = fmaf(dq.x, g0 * g0, acc);
                float g1 = zq.y + nm.y; acc = fmaf(dq.y, g1 * g1, acc);
                float g2 = zq.z + nm.z; acc = fmaf(dq.z, g2 * g2, acc);
                float g3 = zq.w + nm.w; acc = fmaf(dq.w, g3 * g3, acc);
            }
        }
        d2v = acc;
    } else {
        // full quadratic form fallback: d2 = || Sinv^T (mu - z) ||^2
        float acc = 0.0f;
        for (int e = 0; e < ND; e++) {
            float v = 0.0f;
            for (int d = 0; d < ND; d++) {
                float gd = mu[k * ND + d] - zr[d];
                v = fmaf(sinv[(k * ND + d) * ND + e], gd, v);
            }
            acc = fmaf(v, v, acc);
        }
        d2v = acc;
    }
    d2v = fmaxf(d2v, 0.0f);   // MIN_CLAMP

    // ---- softmax(-d2) over K = full warp; deferred normalization ----
    float sc = -d2v;
    float m = sc;
    #pragma unroll
    for (int s = 16; s >= 1; s >>= 1)
        m = fmaxf(m, __shfl_xor_sync(0xffffffffu, m, s));
    float w = __expf(sc - m);        // unnormalized psi weight
    float ssum = w;
    #pragma unroll
    for (int s = 16; s >= 1; s >>= 1)
        ssum += __shfl_xor_sync(0xffffffffu, ssum, s);
    if (k == 0) rinv_s[bl] = 1.0f / ssum;

    // ---- exogenous drive (scalar, same e-order as always) ----
    float ex = bias_s[k];
    #pragma unroll
    for (int e = 0; e < NE; e++)
        ex = fmaf(u_s[bl][e], Bx_s[k][e], ex);

    // ---- AR recurrence: scalar, circular history (compile-time idx) ----
    float a[NORD], h[NORD];
    #pragma unroll
    for (int o = 0; o < NORD; o++) {
        a[o] = A_s[k][o];
        h[o] = yh_s[bl][o];
    }

    #pragma unroll
    for (int s = 0; s < NT; s++) {
        float n = ex;
        #pragma unroll
        for (int o = 0; o < NORD; o++)
            n = fmaf(h[(s + o) & 7], a[o], n);
        h[s & 7] = n;
        float part = w * n;
        part += __shfl_xor_sync(0xffffffffu, part, 16);
        part += __shfl_xor_sync(0xffffffffu, part, 8);
        part += __shfl_xor_sync(0xffffffffu, part, 4);
        if (k < 4) part2[bl][k][s] = part;
    }
    __syncthreads();

    // ---- final reduce (4 partials per b), normalize, float4 store ----
    if (t < TB * NT / 4) {             // 48 threads
        int row = t / (NT / 4);
        int q   = t % (NT / 4);
        float rin = rinv_s[row];
        float4 p0 = *reinterpret_cast<const float4*>(&part2[row][0][q * 4]);
        float4 p1 = *reinterpret_cast<const float4*>(&part2[row][1][q * 4]);
        float4 p2 = *reinterpret_cast<const float4*>(&part2[row][2][q * 4]);
        float4 p3 = *reinterpret_cast<const float4*>(&part2[row][3][q * 4]);
        float4 v = make_float4(((p0.x + p1.x) + (p2.x + p3.x)) * rin,
                               ((p0.y + p1.y) + (p2.y + p3.y)) * rin,
                               ((p0.z + p1.z) + (p2.z + p3.z)) * rin,
                               ((p0.w + p1.w) + (p2.w + p3.w)) * rin);
        *reinterpret_cast<float4*>(out + (b0 + row) * NT + q * 4) = v;
    }
}

// Safety net: only used if out_size exceeds the expected layout.
__global__ void zero_extra_kernel(float* __restrict__ out, int n0, int n) {
    int i = n0 + blockIdx.x * blockDim.x + threadIdx.x;
    if (i < n) out[i] = 0.0f;
}

extern "C" void kernel_launch(void* const* d_in, const int* in_sizes, int n_in,
                              void* d_out, int out_size) {
    const float* y    = (const float*)d_in[0];
    const float* z    = (const float*)d_in[1];
    const float* u    = (const float*)d_in[2];
    const float* mu   = (const float*)d_in[3];
    const float* sinv = (const float*)d_in[4];
    const float* A    = (const float*)d_in[5];
    const float* Bx   = (const float*)d_in[6];
    const float* bias = (const float*)d_in[7];
    float* out = (float*)d_out;

    prep_kernel<<<NK * 32, 128>>>(sinv, mu);
    fused_kernel<<<NB / TB, THREADS>>>(y, z, u, mu, sinv, A, Bx, bias, out);

    int n0 = NB * (NT + NIN);  // fused zeroes [NB*NT, NB*(NT+NIN))
    if (out_size > n0) {
        int extra = out_size - n0;
        zero_extra_kernel<<<(extra + 255) / 256, 256>>>(out, n0, out_size);
    }
}